// round 3
// baseline (speedup 1.0000x reference)
#include <cuda_runtime.h>

// ---------------------------------------------------------------------------
// GATNet: 2-layer GAT, N=50000 nodes, E=800000 edges (+N self loops).
// Layer1: Fin=128 -> HID=64, Layer2: HID=64 -> C=121, sigmoid output.
//
// edge_index dtype is detected at runtime (JAX demotes int64->int32 unless
// x64 is enabled); indices are converted once into an int32 device array.
// Softmax max-subtraction removed: logits are bounded (|e| <= ~8), exp is
// fp32-safe, result mathematically identical.
// ---------------------------------------------------------------------------

#define N_NODES 50000
#define F_IN    128
#define HID     64
#define C_OUT   121
#define E_RAW   800000
#define E_TOT   (E_RAW + N_NODES)

// Scratch (static device globals -- allocation is forbidden)
__device__ int   g_edge[2 * E_RAW];       // int32 src | dst
__device__ int   g_is32;                  // 1 if input edge_index is int32
__device__ float g_h1 [N_NODES * HID];    // x @ W1
__device__ float g_acc1[N_NODES * HID];   // layer1 aggregation
__device__ float g_hW2[N_NODES * C_OUT];  // relu(acc1+b1) @ W2
__device__ float g_as [N_NODES];          // alpha_src (reused per layer)
__device__ float g_ad [N_NODES];          // alpha_dst (reused per layer)
__device__ float g_e  [E_TOT];            // exp weights -> normalized att
__device__ float g_d  [N_NODES];          // segment sum (denominator)

// ---------------- dtype detection + index conversion -----------------------
// If stored as int64 (values < 2^31), every odd 32-bit word is 0.
// If stored as int32, odd words are random node ids -> nonzero w.h.p.
// Only words with index < 2*E_RAW are touched: in-bounds for BOTH layouts.
__global__ void k_detect(const unsigned* __restrict__ ei32) {
    __shared__ int found;
    if (threadIdx.x == 0) found = 0;
    __syncthreads();
    int local = 0;
    for (int k = threadIdx.x; k < 4096; k += blockDim.x) {
        const int j = k * (E_RAW / 4096);        // j in [0, E_RAW)
        if (ei32[2 * j + 1] != 0u) local = 1;
    }
    if (local) found = 1;
    __syncthreads();
    if (threadIdx.x == 0) g_is32 = found;
}

__global__ void k_convert(const void* __restrict__ ei) {
    const int i = blockIdx.x * blockDim.x + threadIdx.x;
    if (i >= 2 * E_RAW) return;
    const int v = g_is32 ? ((const int*)ei)[i]
                         : (int)((const long long*)ei)[i];
    g_edge[i] = v;
}

// ---------------- GEMM 1: h1 = x @ W1, alpha_src/dst per node --------------
__global__ void k_gemm1(const float* __restrict__ x,
                        const float* __restrict__ W1,
                        const float* __restrict__ a_src,
                        const float* __restrict__ a_dst) {
    __shared__ float xs[F_IN];
    __shared__ float r1[HID], r2[HID];
    const int node = blockIdx.x;
    const int f = threadIdx.x;  // 0..63
    xs[f]       = x[node * F_IN + f];
    xs[f + HID] = x[node * F_IN + f + HID];
    __syncthreads();
    float acc = 0.f;
#pragma unroll 16
    for (int k = 0; k < F_IN; k++) acc += xs[k] * W1[k * HID + f];
    g_h1[node * HID + f] = acc;
    r1[f] = acc * a_src[f];
    r2[f] = acc * a_dst[f];
    __syncthreads();
    for (int s = HID / 2; s > 0; s >>= 1) {
        if (f < s) { r1[f] += r1[f + s]; r2[f] += r2[f + s]; }
        __syncthreads();
    }
    if (f == 0) { g_as[node] = r1[0]; g_ad[node] = r2[0]; }
}

// ---------------- init: zero accumulators + denominators -------------------
__global__ void k_init1() {
    const int stride = gridDim.x * blockDim.x;
    const int i0 = blockIdx.x * blockDim.x + threadIdx.x;
    for (int t = i0; t < N_NODES * HID; t += stride) g_acc1[t] = 0.f;
    for (int t = i0; t < N_NODES; t += stride) g_d[t] = 0.f;
}
__global__ void k_init2(float* __restrict__ out) {
    const int stride = gridDim.x * blockDim.x;
    const int i0 = blockIdx.x * blockDim.x + threadIdx.x;
    for (int t = i0; t < N_NODES * C_OUT; t += stride) out[t] = 0.f;
    for (int t = i0; t < N_NODES; t += stride) g_d[t] = 0.f;
}

// ---------------- edge pass A: w = exp(leaky(as+ad)); denom += w -----------
__global__ void k_edge_exp() {
    const int i = blockIdx.x * blockDim.x + threadIdx.x;
    if (i >= E_TOT) return;
    int s, d;
    if (i < E_RAW) { s = g_edge[i]; d = g_edge[E_RAW + i]; }
    else           { s = d = i - E_RAW; }
    float e = g_as[s] + g_ad[d];
    e = (e > 0.f) ? e : 0.2f * e;       // leaky_relu, NEG_SLOPE=0.2
    const float w = __expf(e);
    g_e[i] = w;
    atomicAdd(&g_d[d], w);
}

// ---------------- edge pass A2: normalize attention ------------------------
__global__ void k_edge_norm() {
    const int i = blockIdx.x * blockDim.x + threadIdx.x;
    if (i >= E_TOT) return;
    const int d = (i < E_RAW) ? g_edge[E_RAW + i] : (i - E_RAW);
    g_e[i] = g_e[i] / g_d[d];
}

// ---------------- edge pass B: weighted feature scatter --------------------
// Layer 1: F=64 (64 consecutive threads share one edge; fully coalesced)
__global__ void k_scatter1() {
    const unsigned t = blockIdx.x * blockDim.x + threadIdx.x;
    if (t >= (unsigned)E_TOT * HID) return;
    const unsigned i = t >> 6;
    const unsigned f = t & 63u;
    int s, d;
    if (i < E_RAW) { s = g_edge[i]; d = g_edge[E_RAW + i]; }
    else           { s = d = (int)(i - E_RAW); }
    const float att = g_e[i];
    atomicAdd(&g_acc1[d * HID + f], g_h1[s * HID + f] * att);
}

// Layer 2: F=121
__global__ void k_scatter2(float* __restrict__ out) {
    const unsigned t = blockIdx.x * blockDim.x + threadIdx.x;
    if (t >= (unsigned)E_TOT * C_OUT) return;
    const unsigned i = t / C_OUT;
    const unsigned f = t - i * C_OUT;
    int s, d;
    if (i < E_RAW) { s = g_edge[i]; d = g_edge[E_RAW + i]; }
    else           { s = d = (int)(i - E_RAW); }
    const float att = g_e[i];
    atomicAdd(&out[d * C_OUT + f], g_hW2[s * C_OUT + f] * att);
}

// ---------------- GEMM 2: h2 = relu(acc1+b1) @ W2, alpha2 ------------------
__global__ void k_gemm2(const float* __restrict__ W2,
                        const float* __restrict__ b1,
                        const float* __restrict__ a_src2,
                        const float* __restrict__ a_dst2) {
    __shared__ float hs[HID];
    __shared__ float r1[128], r2[128];
    const int node = blockIdx.x;
    const int f = threadIdx.x;  // 0..127
    if (f < HID) {
        float v = g_acc1[node * HID + f] + b1[f];
        hs[f] = (v > 0.f) ? v : 0.f;
    }
    __syncthreads();
    float acc = 0.f;
    if (f < C_OUT) {
#pragma unroll 16
        for (int k = 0; k < HID; k++) acc += hs[k] * W2[k * C_OUT + f];
        g_hW2[node * C_OUT + f] = acc;
        r1[f] = acc * a_src2[f];
        r2[f] = acc * a_dst2[f];
    } else {
        r1[f] = 0.f; r2[f] = 0.f;
    }
    __syncthreads();
    for (int s = 64; s > 0; s >>= 1) {
        if (f < s) { r1[f] += r1[f + s]; r2[f] += r2[f + s]; }
        __syncthreads();
    }
    if (f == 0) { g_as[node] = r1[0]; g_ad[node] = r2[0]; }
}

// ---------------- finalize: sigmoid(out + b2) ------------------------------
__global__ void k_final(float* __restrict__ out, const float* __restrict__ b2) {
    const int t = blockIdx.x * blockDim.x + threadIdx.x;
    if (t >= N_NODES * C_OUT) return;
    const int f = t % C_OUT;
    const float v = out[t] + b2[f];
    out[t] = 1.f / (1.f + __expf(-v));
}

// ---------------------------------------------------------------------------
extern "C" void kernel_launch(void* const* d_in, const int* in_sizes, int n_in,
                              void* d_out, int out_size) {
    const float* x      = (const float*)d_in[0];
    const void*  ei     = d_in[1];
    const float* W1     = (const float*)d_in[2];
    const float* a_src1 = (const float*)d_in[3];
    const float* a_dst1 = (const float*)d_in[4];
    const float* b1     = (const float*)d_in[5];
    const float* W2     = (const float*)d_in[6];
    const float* a_src2 = (const float*)d_in[7];
    const float* a_dst2 = (const float*)d_in[8];
    const float* b2     = (const float*)d_in[9];
    float*       out    = (float*)d_out;

    const int TPB = 256;
    const int gEdges = (E_TOT + TPB - 1) / TPB;

    // ----- Index dtype detection + conversion -----
    k_detect<<<1, 256>>>((const unsigned*)ei);
    k_convert<<<(2 * E_RAW + TPB - 1) / TPB, TPB>>>(ei);

    // ----- Layer 1 -----
    k_gemm1<<<N_NODES, HID>>>(x, W1, a_src1, a_dst1);
    k_init1<<<512, TPB>>>();
    k_edge_exp<<<gEdges, TPB>>>();
    k_edge_norm<<<gEdges, TPB>>>();
    {
        const unsigned work = (unsigned)E_TOT * HID;
        k_scatter1<<<(work + TPB - 1) / TPB, TPB>>>();
    }

    // ----- Layer 2 -----
    k_gemm2<<<N_NODES, 128>>>(W2, b1, a_src2, a_dst2);
    k_init2<<<512, TPB>>>(out);
    k_edge_exp<<<gEdges, TPB>>>();
    k_edge_norm<<<gEdges, TPB>>>();
    {
        const unsigned work = (unsigned)E_TOT * C_OUT;
        k_scatter2<<<(work + TPB - 1) / TPB, TPB>>>(out);
    }

    // ----- Output -----
    {
        const int total = N_NODES * C_OUT;
        k_final<<<(total + TPB - 1) / TPB, TPB>>>(out, b2);
    }
}

// round 5
// speedup vs baseline: 1.5612x; 1.5612x over previous
#include <cuda_runtime.h>

// ---------------------------------------------------------------------------
// GATNet: 2-layer GAT, N=50000 nodes, E=800000 edges (+N self loops).
// Layer1: Fin=128 -> HID=64, Layer2: HID=64 -> C=121, sigmoid output.
//
// R4 (resubmit; prior round was an infra failure, kernel never ran):
// scatter kernels vectorized to float4 gathers + red.global.add.v4
// (4x fewer LSU/LTS lanes; byte traffic unchanged and L2-resident).
// Layer-2 features padded 121->124 in scratch so every chunk is a float4.
// ---------------------------------------------------------------------------

#define N_NODES 50000
#define F_IN    128
#define HID     64
#define C_OUT   121
#define C_PAD   124                       // 31 float4 chunks
#define E_RAW   800000
#define E_TOT   (E_RAW + N_NODES)

// Scratch (static device globals -- allocation is forbidden)
__device__ int   g_edge[2 * E_RAW];                       // int32 src | dst
__device__ int   g_is32;
__device__ __align__(16) float g_h1  [N_NODES * HID];     // x @ W1
__device__ __align__(16) float g_acc1[N_NODES * HID];     // layer1 aggregation
__device__ __align__(16) float g_hW2 [N_NODES * C_PAD];   // relu(acc1+b1)@W2, padded
__device__ __align__(16) float g_acc2[N_NODES * C_PAD];   // layer2 aggregation, padded
__device__ float g_as [N_NODES];
__device__ float g_ad [N_NODES];
__device__ float g_e  [E_TOT];
__device__ float g_d  [N_NODES];

__device__ __forceinline__ void red_add_v4(float* addr, float4 v) {
    asm volatile("red.global.add.v4.f32 [%0], {%1,%2,%3,%4};"
                 :: "l"(addr), "f"(v.x), "f"(v.y), "f"(v.z), "f"(v.w)
                 : "memory");
}

// ---------------- dtype detection + index conversion -----------------------
// int64 edge ids < 2^31 -> every odd 32-bit word is 0; int32 -> random ids.
__global__ void k_detect(const unsigned* __restrict__ ei32) {
    __shared__ int found;
    if (threadIdx.x == 0) found = 0;
    __syncthreads();
    int local = 0;
    for (int k = threadIdx.x; k < 4096; k += blockDim.x) {
        const int j = k * (E_RAW / 4096);
        if (ei32[2 * j + 1] != 0u) local = 1;
    }
    if (local) found = 1;
    __syncthreads();
    if (threadIdx.x == 0) g_is32 = found;
}

__global__ void k_convert(const void* __restrict__ ei) {
    const int i = blockIdx.x * blockDim.x + threadIdx.x;
    if (i >= 2 * E_RAW) return;
    g_edge[i] = g_is32 ? ((const int*)ei)[i]
                       : (int)((const long long*)ei)[i];
}

// ---------------- GEMM 1: h1 = x @ W1, alpha_src/dst per node --------------
__global__ void k_gemm1(const float* __restrict__ x,
                        const float* __restrict__ W1,
                        const float* __restrict__ a_src,
                        const float* __restrict__ a_dst) {
    __shared__ float xs[F_IN];
    __shared__ float r1[HID], r2[HID];
    const int node = blockIdx.x;
    const int f = threadIdx.x;  // 0..63
    xs[f]       = x[node * F_IN + f];
    xs[f + HID] = x[node * F_IN + f + HID];
    __syncthreads();
    float acc = 0.f;
#pragma unroll 16
    for (int k = 0; k < F_IN; k++) acc += xs[k] * W1[k * HID + f];
    g_h1[node * HID + f] = acc;
    r1[f] = acc * a_src[f];
    r2[f] = acc * a_dst[f];
    __syncthreads();
    for (int s = HID / 2; s > 0; s >>= 1) {
        if (f < s) { r1[f] += r1[f + s]; r2[f] += r2[f + s]; }
        __syncthreads();
    }
    if (f == 0) { g_as[node] = r1[0]; g_ad[node] = r2[0]; }
}

// ---------------- init: zero accumulators + denominators (float4) ----------
__global__ void k_init1() {
    const int stride = gridDim.x * blockDim.x;
    const int i0 = blockIdx.x * blockDim.x + threadIdx.x;
    float4* a = (float4*)g_acc1;
    const float4 z = make_float4(0.f, 0.f, 0.f, 0.f);
    for (int t = i0; t < N_NODES * HID / 4; t += stride) a[t] = z;
    for (int t = i0; t < N_NODES; t += stride) g_d[t] = 0.f;
}
__global__ void k_init2() {
    const int stride = gridDim.x * blockDim.x;
    const int i0 = blockIdx.x * blockDim.x + threadIdx.x;
    float4* a = (float4*)g_acc2;
    const float4 z = make_float4(0.f, 0.f, 0.f, 0.f);
    for (int t = i0; t < N_NODES * C_PAD / 4; t += stride) a[t] = z;
    for (int t = i0; t < N_NODES; t += stride) g_d[t] = 0.f;
}

// ---------------- edge pass A: w = exp(leaky(as+ad)); denom += w -----------
__global__ void k_edge_exp() {
    const int i = blockIdx.x * blockDim.x + threadIdx.x;
    if (i >= E_TOT) return;
    int s, d;
    if (i < E_RAW) { s = g_edge[i]; d = g_edge[E_RAW + i]; }
    else           { s = d = i - E_RAW; }
    float e = g_as[s] + g_ad[d];
    e = (e > 0.f) ? e : 0.2f * e;       // leaky_relu, NEG_SLOPE=0.2
    const float w = __expf(e);
    g_e[i] = w;
    atomicAdd(&g_d[d], w);
}

// ---------------- edge pass A2: normalize attention ------------------------
__global__ void k_edge_norm() {
    const int i = blockIdx.x * blockDim.x + threadIdx.x;
    if (i >= E_TOT) return;
    const int d = (i < E_RAW) ? g_edge[E_RAW + i] : (i - E_RAW);
    g_e[i] = g_e[i] / g_d[d];
}

// ---------------- edge pass B: weighted feature scatter (float4) -----------
// Layer 1: 64 feats = 16 float4 chunks; 16 threads per edge.
__global__ void k_scatter1() {
    const unsigned t = blockIdx.x * blockDim.x + threadIdx.x;
    if (t >= (unsigned)E_TOT * 16) return;
    const unsigned i = t >> 4;
    const unsigned c = t & 15u;
    int s, d;
    if (i < E_RAW) { s = g_edge[i]; d = g_edge[E_RAW + i]; }
    else           { s = d = (int)(i - E_RAW); }
    const float att = g_e[i];
    float4 h = *(const float4*)(g_h1 + s * HID + c * 4);
    h.x *= att; h.y *= att; h.z *= att; h.w *= att;
    red_add_v4(g_acc1 + d * HID + c * 4, h);
}

// Layer 2: 124 padded feats = 31 float4 chunks; 32 threads/edge, lane 31 idle.
__global__ void k_scatter2() {
    const unsigned t = blockIdx.x * blockDim.x + threadIdx.x;
    const unsigned c = t & 31u;
    if (c >= 31u) return;
    if (t >= (unsigned)E_TOT * 32) return;
    const unsigned i = t >> 5;
    int s, d;
    if (i < E_RAW) { s = g_edge[i]; d = g_edge[E_RAW + i]; }
    else           { s = d = (int)(i - E_RAW); }
    const float att = g_e[i];
    float4 h = *(const float4*)(g_hW2 + s * C_PAD + c * 4);
    h.x *= att; h.y *= att; h.z *= att; h.w *= att;
    red_add_v4(g_acc2 + d * C_PAD + c * 4, h);
}

// ---------------- GEMM 2: hW2 = relu(acc1+b1) @ W2, alpha2 -----------------
__global__ void k_gemm2(const float* __restrict__ W2,
                        const float* __restrict__ b1,
                        const float* __restrict__ a_src2,
                        const float* __restrict__ a_dst2) {
    __shared__ float hs[HID];
    __shared__ float r1[128], r2[128];
    const int node = blockIdx.x;
    const int f = threadIdx.x;  // 0..127
    if (f < HID) {
        float v = g_acc1[node * HID + f] + b1[f];
        hs[f] = (v > 0.f) ? v : 0.f;
    }
    __syncthreads();
    float acc = 0.f;
    if (f < C_OUT) {
#pragma unroll 16
        for (int k = 0; k < HID; k++) acc += hs[k] * W2[k * C_OUT + f];
        g_hW2[node * C_PAD + f] = acc;
        r1[f] = acc * a_src2[f];
        r2[f] = acc * a_dst2[f];
    } else {
        if (f < C_PAD) g_hW2[node * C_PAD + f] = 0.f;   // zero padding cols
        r1[f] = 0.f; r2[f] = 0.f;
    }
    __syncthreads();
    for (int s = 64; s > 0; s >>= 1) {
        if (f < s) { r1[f] += r1[f + s]; r2[f] += r2[f + s]; }
        __syncthreads();
    }
    if (f == 0) { g_as[node] = r1[0]; g_ad[node] = r2[0]; }
}

// ---------------- finalize: out = sigmoid(acc2 + b2) -----------------------
__global__ void k_final(float* __restrict__ out, const float* __restrict__ b2) {
    const int t = blockIdx.x * blockDim.x + threadIdx.x;
    if (t >= N_NODES * C_OUT) return;
    const int d = t / C_OUT;
    const int f = t - d * C_OUT;
    const float v = g_acc2[d * C_PAD + f] + b2[f];
    out[t] = 1.f / (1.f + __expf(-v));
}

// ---------------------------------------------------------------------------
extern "C" void kernel_launch(void* const* d_in, const int* in_sizes, int n_in,
                              void* d_out, int out_size) {
    const float* x      = (const float*)d_in[0];
    const void*  ei     = d_in[1];
    const float* W1     = (const float*)d_in[2];
    const float* a_src1 = (const float*)d_in[3];
    const float* a_dst1 = (const float*)d_in[4];
    const float* b1     = (const float*)d_in[5];
    const float* W2     = (const float*)d_in[6];
    const float* a_src2 = (const float*)d_in[7];
    const float* a_dst2 = (const float*)d_in[8];
    const float* b2     = (const float*)d_in[9];
    float*       out    = (float*)d_out;

    const int TPB = 256;
    const int gEdges = (E_TOT + TPB - 1) / TPB;

    // ----- Index dtype detection + conversion -----
    k_detect<<<1, 256>>>((const unsigned*)ei);
    k_convert<<<(2 * E_RAW + TPB - 1) / TPB, TPB>>>(ei);

    // ----- Layer 1 -----
    k_gemm1<<<N_NODES, HID>>>(x, W1, a_src1, a_dst1);
    k_init1<<<512, TPB>>>();
    k_edge_exp<<<gEdges, TPB>>>();
    k_edge_norm<<<gEdges, TPB>>>();
    {
        const unsigned work = (unsigned)E_TOT * 16;
        k_scatter1<<<(work + TPB - 1) / TPB, TPB>>>();
    }

    // ----- Layer 2 -----
    k_gemm2<<<N_NODES, 128>>>(W2, b1, a_src2, a_dst2);
    k_init2<<<512, TPB>>>();
    k_edge_exp<<<gEdges, TPB>>>();
    k_edge_norm<<<gEdges, TPB>>>();
    {
        const unsigned work = (unsigned)E_TOT * 32;
        k_scatter2<<<(work + TPB - 1) / TPB, TPB>>>();
    }

    // ----- Output -----
    {
        const int total = N_NODES * C_OUT;
        k_final<<<(total + TPB - 1) / TPB, TPB>>>(out, b2);
    }
}